// round 2
// baseline (speedup 1.0000x reference)
#include <cuda_runtime.h>
#include <cstdint>

#define BATCH  256
#define IN_DIM 14400
#define KNN    25
#define D0     7200
#define D1     3600
#define D2     1800
#define FC_CHUNKS 40           // 1800 / 40 = 45 d's per chunk

// ---------------- scratch (device globals: alloc-free) ----------------
__device__ float g_xT[2 * IN_DIM * BATCH];   // (28800, 256)  29.5 MB
__device__ float g_a0[2 * D0 * BATCH];       // (2*7200, 256) 14.7 MB
__device__ float g_a1[2 * D1 * BATCH];       // (2*3600, 256)  7.4 MB
__device__ float g_a2[2 * D2 * BATCH];       // (2*1800, 256)  3.7 MB
__device__ float g_partial[FC_CHUNKS * BATCH * 4];

// ---------------- transpose: x (256, 28800) -> g_xT (28800, 256) -------
__global__ void transpose_kernel(const float* __restrict__ x) {
    __shared__ float tile[32][33];
    const int col = blockIdx.x * 32 + threadIdx.x;   // dim index (0..28799)
    const int row = blockIdx.y * 32 + threadIdx.y;   // batch index (0..255)
    tile[threadIdx.y][threadIdx.x] = x[row * (2 * IN_DIM) + col];
    __syncthreads();
    const int odim = blockIdx.x * 32 + threadIdx.y;
    const int ob   = blockIdx.y * 32 + threadIdx.x;
    g_xT[odim * BATCH + ob] = tile[threadIdx.x][threadIdx.y];
}

// ---------------- LCN layer: out[(ch,d), b] = relu(sum_k w*in[knn,b]+bias)
// Block = 4 output d's, 256 threads: tid>>6 selects d, tid&63 is float4 batch lane.
template <int LAYER>
__global__ __launch_bounds__(256)
void lcn_layer_kernel(const int* __restrict__ knn,
                      const float* __restrict__ wp, const float* __restrict__ bp,
                      const float* __restrict__ wn, const float* __restrict__ bn)
{
    constexpr int PREV = (LAYER == 0) ? IN_DIM : (LAYER == 1 ? D0 : D1);
    constexpr int DIM  = (LAYER == 0) ? D0     : (LAYER == 1 ? D1 : D2);
    const float* __restrict__ in  = (LAYER == 0) ? g_xT : (LAYER == 1 ? g_a0 : g_a1);
    float*       __restrict__ out = (LAYER == 0) ? g_a0 : (LAYER == 1 ? g_a1 : g_a2);

    const int ch = blockIdx.y;                       // 0 = pos, 1 = neg
    const int d0 = blockIdx.x * 4;
    const float* __restrict__ w    = ch ? wn : wp;
    const float* __restrict__ bias = ch ? bn : bp;

    __shared__ int   s_off[4][KNN];                  // row offset in float4 units
    __shared__ float s_w[4][KNN];

    const int t = threadIdx.x;
    if (t < 4 * KNN) {
        const int sub = t / KNN, k = t % KNN;
        const int d = d0 + sub;
        const int idx = knn[d * KNN + k] + ch * PREV;
        s_off[sub][k] = idx * (BATCH / 4);
        s_w[sub][k]   = w[d * KNN + k];
    }
    __syncthreads();

    const int sub  = t >> 6;                         // which d of the 4
    const int lane = t & 63;                         // float4 lane over batch
    const int d    = d0 + sub;

    const float4* __restrict__ in4 = (const float4*)in;
    float4 acc = make_float4(0.f, 0.f, 0.f, 0.f);
#pragma unroll
    for (int k = 0; k < KNN; ++k) {
        const float  wv = s_w[sub][k];
        const float4 v  = in4[s_off[sub][k] + lane];
        acc.x += wv * v.x; acc.y += wv * v.y;
        acc.z += wv * v.z; acc.w += wv * v.w;
    }
    const float bv = bias[d];
    acc.x = fmaxf(acc.x + bv, 0.f);
    acc.y = fmaxf(acc.y + bv, 0.f);
    acc.z = fmaxf(acc.z + bv, 0.f);
    acc.w = fmaxf(acc.w + bv, 0.f);

    ((float4*)out)[(ch * DIM + d) * (BATCH / 4) + lane] = acc;
}

// ---------------- FC over d (partial sums across 40 chunks) ------------
__global__ __launch_bounds__(256)
void fc_partial_kernel(const float* __restrict__ fcp_w,
                       const float* __restrict__ fcn_w)
{
    const int b = threadIdx.x;
    const int c = blockIdx.x;
    const int dstart = c * (D2 / FC_CHUNKS);
    float p0 = 0.f, p1 = 0.f, n0 = 0.f, n1 = 0.f;
#pragma unroll 5
    for (int d = dstart; d < dstart + D2 / FC_CHUNKS; ++d) {
        const float ap = g_a2[d * BATCH + b];
        const float an = g_a2[(D2 + d) * BATCH + b];
        p0 += ap * fcp_w[d];
        p1 += ap * fcp_w[D2 + d];
        n0 += an * fcn_w[d];
        n1 += an * fcn_w[D2 + d];
    }
    ((float4*)g_partial)[c * BATCH + b] = make_float4(p0, p1, n0, n1);
}

__global__ void fc_final_kernel(const float* __restrict__ fcp_b,
                                const float* __restrict__ fcn_b,
                                const float* __restrict__ fc3_w,
                                const float* __restrict__ fc3_b,
                                float* __restrict__ out)
{
    const int b = threadIdx.x;
    float h0 = fcp_b[0], h1 = fcp_b[1], h2 = fcn_b[0], h3 = fcn_b[1];
#pragma unroll
    for (int c = 0; c < FC_CHUNKS; ++c) {
        const float4 r = ((const float4*)g_partial)[c * BATCH + b];
        h0 += r.x; h1 += r.y; h2 += r.z; h3 += r.w;
    }
    h0 = fmaxf(h0, 0.f); h1 = fmaxf(h1, 0.f);
    h2 = fmaxf(h2, 0.f); h3 = fmaxf(h3, 0.f);
    out[b * 2 + 0] = fc3_b[0] + fc3_w[0] * h0 + fc3_w[1] * h1 + fc3_w[2] * h2 + fc3_w[3] * h3;
    out[b * 2 + 1] = fc3_b[1] + fc3_w[4] * h0 + fc3_w[5] * h1 + fc3_w[6] * h2 + fc3_w[7] * h3;
}

// ---------------- launcher ---------------------------------------------
extern "C" void kernel_launch(void* const* d_in, const int* in_sizes, int n_in,
                              void* d_out, int out_size)
{
    const float* x    = (const float*)d_in[0];
    const int*   knn0 = (const int*)d_in[1];
    const int*   knn1 = (const int*)d_in[2];
    const int*   knn2 = (const int*)d_in[3];
    const float* wp0 = (const float*)d_in[4];
    const float* bp0 = (const float*)d_in[5];
    const float* wp1 = (const float*)d_in[6];
    const float* bp1 = (const float*)d_in[7];
    const float* wp2 = (const float*)d_in[8];
    const float* bp2 = (const float*)d_in[9];
    const float* fcp_w = (const float*)d_in[10];
    const float* fcp_b = (const float*)d_in[11];
    const float* wn0 = (const float*)d_in[12];
    const float* bn0 = (const float*)d_in[13];
    const float* wn1 = (const float*)d_in[14];
    const float* bn1 = (const float*)d_in[15];
    const float* wn2 = (const float*)d_in[16];
    const float* bn2 = (const float*)d_in[17];
    const float* fcn_w = (const float*)d_in[18];
    const float* fcn_b = (const float*)d_in[19];
    const float* fc3_w = (const float*)d_in[20];
    const float* fc3_b = (const float*)d_in[21];
    float* out = (float*)d_out;

    transpose_kernel<<<dim3((2 * IN_DIM) / 32, BATCH / 32), dim3(32, 32)>>>(x);

    lcn_layer_kernel<0><<<dim3(D0 / 4, 2), 256>>>(knn0, wp0, bp0, wn0, bn0);
    lcn_layer_kernel<1><<<dim3(D1 / 4, 2), 256>>>(knn1, wp1, bp1, wn1, bn1);
    lcn_layer_kernel<2><<<dim3(D2 / 4, 2), 256>>>(knn2, wp2, bp2, wn2, bn2);

    fc_partial_kernel<<<FC_CHUNKS, 256>>>(fcp_w, fcn_w);
    fc_final_kernel<<<1, 256>>>(fcp_b, fcn_b, fc3_w, fc3_b, out);
}

// round 3
// speedup vs baseline: 1.7021x; 1.7021x over previous
#include <cuda_runtime.h>
#include <cuda_fp16.h>
#include <cstdint>

#define BATCH  256
#define IN_DIM 14400
#define KNN    25
#define D0     7200
#define D1     3600
#define D2     1800
#define FC_CHUNKS 40           // 1800 / 40 = 45 d's per chunk

// ---------------- scratch (device globals: alloc-free) ----------------
__device__ __align__(16) __half g_xT[2 * IN_DIM * BATCH];  // (28800,256) fp16, 14.7MB
__device__ __align__(16) __half g_a0[2 * D0 * BATCH];      // 7.4MB
__device__ __align__(16) __half g_a1[2 * D1 * BATCH];      // 3.7MB
__device__ __align__(16) __half g_a2[2 * D2 * BATCH];      // 1.8MB
__device__ float g_partial[FC_CHUNKS * BATCH * 4];

// ---------------- transpose: x (256, 28800) fp32 -> g_xT (28800, 256) fp16
// Tile: 32 batch x 128 dim. Block 256 threads, grid (225, 8).
__global__ __launch_bounds__(256)
void transpose_kernel(const float* __restrict__ x) {
    __shared__ float s[32][132];                 // 132-float row stride: 16B aligned, conflict-free
    const int t = threadIdx.x;
    const int dbase = blockIdx.x * 128;
    const int bbase = blockIdx.y * 32;

    // load: 4 float4 per thread, coalesced along dim
    const int fc = t & 31;                       // float4 col within 128-dim tile
    const int r  = t >> 5;                       // 0..7
    const float4* __restrict__ x4 = (const float4*)x;
#pragma unroll
    for (int rr = 0; rr < 4; ++rr) {
        const int row = rr * 8 + r;              // batch row within tile
        float4 v = x4[(size_t)(bbase + row) * (2 * IN_DIM / 4) + (dbase / 4) + fc];
        *(float4*)&s[row][fc * 4] = v;
    }
    __syncthreads();

    // store: 2 uint4 (8 halfs = 8 batch elems) per thread, coalesced along batch
    const int d = t & 127;
    const int h = t >> 7;                        // 0..1
    uint4* __restrict__ o4 = (uint4*)g_xT;
#pragma unroll
    for (int hh = 0; hh < 2; ++hh) {
        const int q  = hh * 2 + h;               // 0..3
        const int b0 = q * 8;
        __half2 p0 = __floats2half2_rn(s[b0 + 0][d], s[b0 + 1][d]);
        __half2 p1 = __floats2half2_rn(s[b0 + 2][d], s[b0 + 3][d]);
        __half2 p2 = __floats2half2_rn(s[b0 + 4][d], s[b0 + 5][d]);
        __half2 p3 = __floats2half2_rn(s[b0 + 6][d], s[b0 + 7][d]);
        uint4 o;
        o.x = *(uint32_t*)&p0; o.y = *(uint32_t*)&p1;
        o.z = *(uint32_t*)&p2; o.w = *(uint32_t*)&p3;
        o4[(((size_t)(dbase + d)) * BATCH + bbase + b0) >> 3] = o;
    }
}

// ---------------- LCN layer (fp16 in/out, fp32 accumulate) -------------
// Block = 8 output d's x 32 lanes (each lane = 8 batch elems via uint4).
template <int LAYER>
__global__ __launch_bounds__(256)
void lcn_layer_kernel(const int* __restrict__ knn,
                      const float* __restrict__ wp, const float* __restrict__ bp,
                      const float* __restrict__ wn, const float* __restrict__ bn)
{
    constexpr int PREV = (LAYER == 0) ? IN_DIM : (LAYER == 1 ? D0 : D1);
    constexpr int DIM  = (LAYER == 0) ? D0     : (LAYER == 1 ? D1 : D2);
    const __half* __restrict__ in  = (LAYER == 0) ? g_xT : (LAYER == 1 ? g_a0 : g_a1);
    __half*       __restrict__ out = (LAYER == 0) ? g_a0 : (LAYER == 1 ? g_a1 : g_a2);

    const int ch = blockIdx.y;
    const int d0 = blockIdx.x * 8;
    const float* __restrict__ w    = ch ? wn : wp;
    const float* __restrict__ bias = ch ? bn : bp;

    __shared__ int   s_off[8][KNN];              // row offset in uint4 units
    __shared__ float s_w[8][KNN];

    const int t = threadIdx.x;
    if (t < 8 * KNN) {
        const int sub = t / KNN, k = t % KNN;
        const int d = d0 + sub;
        s_off[sub][k] = (knn[d * KNN + k] + ch * PREV) * (BATCH / 8);
        s_w[sub][k]   = w[d * KNN + k];
    }
    __syncthreads();

    const int sub  = t >> 5;                     // which d (0..7)
    const int lane = t & 31;                     // uint4 lane over batch
    const int d    = d0 + sub;

    const uint4* __restrict__ in4 = (const uint4*)in;

    // 6-deep prefetch pipeline -> >=6 outstanding LDG.128 per thread
    uint4 vbuf[6];
#pragma unroll
    for (int k = 0; k < 6; ++k) vbuf[k] = in4[s_off[sub][k] + lane];

    float a0 = 0.f, a1 = 0.f, a2 = 0.f, a3 = 0.f;
    float a4 = 0.f, a5 = 0.f, a6 = 0.f, a7 = 0.f;
#pragma unroll
    for (int k = 0; k < KNN; ++k) {
        uint4 v = vbuf[k % 6];
        if (k + 6 < KNN) vbuf[k % 6] = in4[s_off[sub][k + 6] + lane];
        const float wv = s_w[sub][k];
        float2 f0 = __half22float2(*(const __half2*)&v.x);
        float2 f1 = __half22float2(*(const __half2*)&v.y);
        float2 f2 = __half22float2(*(const __half2*)&v.z);
        float2 f3 = __half22float2(*(const __half2*)&v.w);
        a0 += wv * f0.x; a1 += wv * f0.y;
        a2 += wv * f1.x; a3 += wv * f1.y;
        a4 += wv * f2.x; a5 += wv * f2.y;
        a6 += wv * f3.x; a7 += wv * f3.y;
    }
    const float bv = bias[d];
    a0 = fmaxf(a0 + bv, 0.f); a1 = fmaxf(a1 + bv, 0.f);
    a2 = fmaxf(a2 + bv, 0.f); a3 = fmaxf(a3 + bv, 0.f);
    a4 = fmaxf(a4 + bv, 0.f); a5 = fmaxf(a5 + bv, 0.f);
    a6 = fmaxf(a6 + bv, 0.f); a7 = fmaxf(a7 + bv, 0.f);

    __half2 p0 = __floats2half2_rn(a0, a1);
    __half2 p1 = __floats2half2_rn(a2, a3);
    __half2 p2 = __floats2half2_rn(a4, a5);
    __half2 p3 = __floats2half2_rn(a6, a7);
    uint4 o;
    o.x = *(uint32_t*)&p0; o.y = *(uint32_t*)&p1;
    o.z = *(uint32_t*)&p2; o.w = *(uint32_t*)&p3;
    ((uint4*)out)[(size_t)(ch * DIM + d) * (BATCH / 8) + lane] = o;
}

// ---------------- FC over d (partial sums across 40 chunks) ------------
__global__ __launch_bounds__(256)
void fc_partial_kernel(const float* __restrict__ fcp_w,
                       const float* __restrict__ fcn_w)
{
    const int b = threadIdx.x;
    const int c = blockIdx.x;
    const int dstart = c * (D2 / FC_CHUNKS);
    float p0 = 0.f, p1 = 0.f, n0 = 0.f, n1 = 0.f;
#pragma unroll 5
    for (int d = dstart; d < dstart + D2 / FC_CHUNKS; ++d) {
        const float ap = __half2float(g_a2[d * BATCH + b]);
        const float an = __half2float(g_a2[(D2 + d) * BATCH + b]);
        p0 += ap * fcp_w[d];
        p1 += ap * fcp_w[D2 + d];
        n0 += an * fcn_w[d];
        n1 += an * fcn_w[D2 + d];
    }
    ((float4*)g_partial)[c * BATCH + b] = make_float4(p0, p1, n0, n1);
}

__global__ void fc_final_kernel(const float* __restrict__ fcp_b,
                                const float* __restrict__ fcn_b,
                                const float* __restrict__ fc3_w,
                                const float* __restrict__ fc3_b,
                                float* __restrict__ out)
{
    const int b = threadIdx.x;
    float h0 = fcp_b[0], h1 = fcp_b[1], h2 = fcn_b[0], h3 = fcn_b[1];
#pragma unroll
    for (int c = 0; c < FC_CHUNKS; ++c) {
        const float4 r = ((const float4*)g_partial)[c * BATCH + b];
        h0 += r.x; h1 += r.y; h2 += r.z; h3 += r.w;
    }
    h0 = fmaxf(h0, 0.f); h1 = fmaxf(h1, 0.f);
    h2 = fmaxf(h2, 0.f); h3 = fmaxf(h3, 0.f);
    out[b * 2 + 0] = fc3_b[0] + fc3_w[0] * h0 + fc3_w[1] * h1 + fc3_w[2] * h2 + fc3_w[3] * h3;
    out[b * 2 + 1] = fc3_b[1] + fc3_w[4] * h0 + fc3_w[5] * h1 + fc3_w[6] * h2 + fc3_w[7] * h3;
}

// ---------------- launcher ---------------------------------------------
extern "C" void kernel_launch(void* const* d_in, const int* in_sizes, int n_in,
                              void* d_out, int out_size)
{
    const float* x    = (const float*)d_in[0];
    const int*   knn0 = (const int*)d_in[1];
    const int*   knn1 = (const int*)d_in[2];
    const int*   knn2 = (const int*)d_in[3];
    const float* wp0 = (const float*)d_in[4];
    const float* bp0 = (const float*)d_in[5];
    const float* wp1 = (const float*)d_in[6];
    const float* bp1 = (const float*)d_in[7];
    const float* wp2 = (const float*)d_in[8];
    const float* bp2 = (const float*)d_in[9];
    const float* fcp_w = (const float*)d_in[10];
    const float* fcp_b = (const float*)d_in[11];
    const float* wn0 = (const float*)d_in[12];
    const float* bn0 = (const float*)d_in[13];
    const float* wn1 = (const float*)d_in[14];
    const float* bn1 = (const float*)d_in[15];
    const float* wn2 = (const float*)d_in[16];
    const float* bn2 = (const float*)d_in[17];
    const float* fcn_w = (const float*)d_in[18];
    const float* fcn_b = (const float*)d_in[19];
    const float* fc3_w = (const float*)d_in[20];
    const float* fc3_b = (const float*)d_in[21];
    float* out = (float*)d_out;

    transpose_kernel<<<dim3((2 * IN_DIM) / 128, BATCH / 32), 256>>>(x);

    lcn_layer_kernel<0><<<dim3(D0 / 8, 2), 256>>>(knn0, wp0, bp0, wn0, bn0);
    lcn_layer_kernel<1><<<dim3(D1 / 8, 2), 256>>>(knn1, wp1, bp1, wn1, bn1);
    lcn_layer_kernel<2><<<dim3(D2 / 8, 2), 256>>>(knn2, wp2, bp2, wn2, bn2);

    fc_partial_kernel<<<FC_CHUNKS, 256>>>(fcp_w, fcn_w);
    fc_final_kernel<<<1, 256>>>(fcp_b, fcn_b, fc3_w, fc3_b, out);
}